// round 10
// baseline (speedup 1.0000x reference)
#include <cuda_runtime.h>
#include <cuda_bf16.h>
#include <stdint.h>

#define NN 8192
#define NE 262144
#define CC 512
#define KX   1024   // x split: [xh | xl]
#define KW   1536   // w split: [wh | wh | wl]
#define KTILES 24   // KW / 64 (x k-tiles 16..23 remap to block0 = xh)

// ---------------- device scratch ----------------
__device__ unsigned      g_bitmap[(size_t)NN * NN / 32];     // 8 MiB adjacency bitmap
__device__ int           g_deg[NN];
__device__ float         g_dis[NN];
__device__ float         g_g[(size_t)NN * CC];               // dis[m]*(xW^T+b), 16 MiB
__device__ __nv_bfloat16 g_xcat[(size_t)NN * KX];            // [xh | xl], 16 MiB
__device__ __nv_bfloat16 g_wcat[(size_t)CC * KW];            // [wh | wh | wl], 1.5 MiB

// ---------------- PTX helpers (baseline PTX only: sm_80-era features) ----------------
__device__ __forceinline__ uint32_t smem_u32(const void* p) {
    uint32_t a;
    asm("{ .reg .u64 t; cvta.to.shared.u64 t, %1; cvt.u32.u64 %0, t; }" : "=r"(a) : "l"(p));
    return a;
}
#define CP_ASYNC16(dst, src) \
    asm volatile("cp.async.cg.shared.global [%0], [%1], 16;" :: "r"(dst), "l"(src) : "memory")
#define CP_COMMIT()  asm volatile("cp.async.commit_group;" ::: "memory")
#define CP_WAIT(N)   asm volatile("cp.async.wait_group %0;" :: "n"(N) : "memory")

#define LDM_X4(r, addr)                                                          \
    asm volatile("ldmatrix.sync.aligned.m8n8.x4.shared.b16 {%0,%1,%2,%3}, [%4];" \
        : "=r"((r)[0]), "=r"((r)[1]), "=r"((r)[2]), "=r"((r)[3]) : "r"(addr))

#define MMA16816(d, a, b0v, b1v)                                                  \
    asm volatile("mma.sync.aligned.m16n8k16.row.col.f32.bf16.bf16.f32 "           \
        "{%0,%1,%2,%3}, {%4,%5,%6,%7}, {%8,%9}, {%0,%1,%2,%3};"                   \
        : "+f"((d)[0]), "+f"((d)[1]), "+f"((d)[2]), "+f"((d)[3])                  \
        : "r"((a)[0]), "r"((a)[1]), "r"((a)[2]), "r"((a)[3]), "r"(b0v), "r"(b1v))

// ---------------- kernel 1: clear bitmap + deg ----------------
__global__ __launch_bounds__(256) void k_clear() {
    int t = blockIdx.x * blockDim.x + threadIdx.x;
    ((uint4*)g_bitmap)[t] = make_uint4(0u, 0u, 0u, 0u);
    if (t < NN) g_deg[t] = 0;
}

// ---------------- kernel 2: dedup edges (+ self loops), degrees ----------------
__global__ __launch_bounds__(256) void k_dedup(const void* __restrict__ eraw) {
    const int* e32 = (const int*)eraw;
    bool is64 = (e32[1] == 0) && (e32[3] == 0) && (e32[5] == 0) && (e32[7] == 0);
    int e = blockIdx.x * blockDim.x + threadIdx.x;
    if (e >= NE + NN) return;
    int r, c;
    if (e < NE) {
        if (is64) {
            const long long* e64 = (const long long*)eraw;
            r = (int)e64[e]; c = (int)e64[NE + e];
        } else {
            r = e32[e]; c = e32[NE + e];
        }
    } else {
        r = c = e - NE;
    }
    r &= (NN - 1); c &= (NN - 1);
    unsigned idx  = (unsigned)r * (unsigned)NN + (unsigned)c;
    unsigned mask = 1u << (idx & 31u);
    unsigned old  = atomicOr(&g_bitmap[idx >> 5], mask);
    if (!(old & mask)) atomicAdd(&g_deg[r], 1);
}

// ---------------- kernel 3 (fused): dis + convX + convW, vectorized ----------------
// convX: blocks [0, 4096) | convW: blocks [4096, 4352) | dis: blocks [4352, 4384)
__device__ __forceinline__ void split4(float4 v, uint2& hp, uint2& lp) {
    __nv_bfloat16 h0 = __float2bfloat16(v.x), h1 = __float2bfloat16(v.y);
    __nv_bfloat16 h2 = __float2bfloat16(v.z), h3 = __float2bfloat16(v.w);
    __nv_bfloat16 l0 = __float2bfloat16(v.x - __bfloat162float(h0));
    __nv_bfloat16 l1 = __float2bfloat16(v.y - __bfloat162float(h1));
    __nv_bfloat16 l2 = __float2bfloat16(v.z - __bfloat162float(h2));
    __nv_bfloat16 l3 = __float2bfloat16(v.w - __bfloat162float(h3));
    union { __nv_bfloat162 b[2]; uint2 u; } H, L;
    H.b[0] = __halves2bfloat162(h0, h1); H.b[1] = __halves2bfloat162(h2, h3);
    L.b[0] = __halves2bfloat162(l0, l1); L.b[1] = __halves2bfloat162(l2, l3);
    hp = H.u; lp = L.u;
}
__global__ __launch_bounds__(256) void k_prep(const float* __restrict__ x,
                                              const float* __restrict__ W) {
    int bid = blockIdx.x;
    if (bid < 4096) {                         // ---- convX ----
        int t = bid * 256 + threadIdx.x;
        int e = t * 4;
        int m = e >> 9, k = e & 511;
        uint2 hp, lp;
        split4(*(const float4*)(x + e), hp, lp);
        size_t rb = (size_t)m * KX;
        *(uint2*)&g_xcat[rb + k]       = hp;
        *(uint2*)&g_xcat[rb + 512 + k] = lp;
    } else if (bid < 4352) {                  // ---- convW ----
        int t = (bid - 4096) * 256 + threadIdx.x;
        int e = t * 4;
        int n = e >> 9, k = e & 511;
        uint2 hp, lp;
        split4(*(const float4*)(W + e), hp, lp);
        size_t rb = (size_t)n * KW;
        *(uint2*)&g_wcat[rb + k]        = hp;
        *(uint2*)&g_wcat[rb + 512 + k]  = hp;
        *(uint2*)&g_wcat[rb + 1024 + k] = lp;
    } else {                                  // ---- dis ----
        int i = (bid - 4352) * 256 + threadIdx.x;
        if (i < NN) g_dis[i] = rsqrtf((float)g_deg[i]);
    }
}

// ---------------- kernel 4: mma.sync GEMM with register-pipelined fragments ----------------
// CTA tile 128(M) x 128(N) x 64(K), 8 warps (4M x 2N), warp tile 32x64,
// cp.async 3-stage smem pipeline + 2-deep register fragment pipeline:
// ldmatrix for k-step ks+1 issues before the MMAs of ks, hiding LDS latency.
struct Frag {
    uint32_t ra[2][4];
    uint32_t rb[4][4];
};
__device__ __forceinline__ void load_frags(Frag& f, uint32_t abase, uint32_t bbase,
                                           int c16, int warp_m, int warp_n, int lrow) {
#pragma unroll
    for (int mt = 0; mt < 2; mt++) {
        int row = warp_m * 32 + mt * 16 + lrow;
        LDM_X4(f.ra[mt], abase + row * 128 + ((c16 ^ (row & 7)) << 4));
    }
#pragma unroll
    for (int np = 0; np < 4; np++) {
        int row = warp_n * 64 + np * 16 + lrow;
        LDM_X4(f.rb[np], bbase + row * 128 + ((c16 ^ (row & 7)) << 4));
    }
}

__device__ __forceinline__ void gemm_load_stage(uint32_t sbase, int stage, int kt,
                                                const __nv_bfloat16* xa0,
                                                const __nv_bfloat16* wa0, int tid) {
    int xkt = (kt < 16) ? kt : kt - 16;       // k-tiles 16..23 reuse xh block
    const __nv_bfloat16* xa = xa0 + xkt * 64;
    const __nv_bfloat16* wa = wa0 + kt * 64;
    uint32_t abase = sbase + stage * 32768;
    uint32_t bbase = abase + 16384;
#pragma unroll
    for (int j = 0; j < 4; j++) {
        int u = tid * 4 + j;                  // 0..1023 : 128 rows x 8 units
        int row = u >> 3, c16 = u & 7;
        uint32_t so = row * 128 + ((uint32_t)(c16 ^ (row & 7)) << 4);
        CP_ASYNC16(abase + so, xa + (size_t)row * KX + c16 * 8);
        CP_ASYNC16(bbase + so, wa + (size_t)row * KW + c16 * 8);
    }
    CP_COMMIT();
}

__global__ __launch_bounds__(256) void k_gemm_mma(const float* __restrict__ b) {
    extern __shared__ char sm[];
    const int tid    = threadIdx.x;
    const int wid    = tid >> 5;
    const int lane   = tid & 31;
    const int warp_m = wid & 3;
    const int warp_n = wid >> 2;
    const int n0     = blockIdx.x * 128;
    const int m0     = blockIdx.y * 128;
    const uint32_t sbase = smem_u32(sm);

    const __nv_bfloat16* xa0 = g_xcat + (size_t)m0 * KX;
    const __nv_bfloat16* wa0 = g_wcat + (size_t)n0 * KW;

    float acc[2][8][4];
#pragma unroll
    for (int mt = 0; mt < 2; mt++)
#pragma unroll
        for (int nt = 0; nt < 8; nt++)
#pragma unroll
            for (int q = 0; q < 4; q++) acc[mt][nt][q] = 0.f;

    gemm_load_stage(sbase, 0, 0, xa0, wa0, tid);
    gemm_load_stage(sbase, 1, 1, xa0, wa0, tid);
    gemm_load_stage(sbase, 2, 2, xa0, wa0, tid);

    const int lrow  = lane & 15;
    const int lhalf = lane >> 4;

    Frag fr[2];

#pragma unroll 1
    for (int kt = 0; kt < KTILES; kt++) {
        if (kt < KTILES - 2)       { CP_WAIT(2); }
        else if (kt == KTILES - 2) { CP_WAIT(1); }
        else                       { CP_WAIT(0); }
        __syncthreads();

        int      stage = kt % 3;
        uint32_t abase = sbase + stage * 32768;
        uint32_t bbase = abase + 16384;

        load_frags(fr[0], abase, bbase, lhalf, warp_m, warp_n, lrow);

#pragma unroll
        for (int ks = 0; ks < 4; ks++) {
            int cur = ks & 1;
            if (ks < 3)
                load_frags(fr[cur ^ 1], abase, bbase, (ks + 1) * 2 + lhalf,
                           warp_m, warp_n, lrow);
#pragma unroll
            for (int mt = 0; mt < 2; mt++)
#pragma unroll
                for (int nt = 0; nt < 8; nt++) {
                    int p = nt >> 1, s = nt & 1;
                    MMA16816(acc[mt][nt], fr[cur].ra[mt],
                             fr[cur].rb[p][s], fr[cur].rb[p][s + 2]);
                }
        }
        __syncthreads();
        if (kt + 3 < KTILES) gemm_load_stage(sbase, stage, kt + 3, xa0, wa0, tid);
    }

    // epilogue: acc -> g_g with dis[m] scale and b[n] bias.
#pragma unroll
    for (int mt = 0; mt < 2; mt++) {
        int   r0 = m0 + warp_m * 32 + mt * 16 + (lane >> 2);
        int   r1 = r0 + 8;
        float d0 = g_dis[r0], d1 = g_dis[r1];
#pragma unroll
        for (int nt = 0; nt < 8; nt++) {
            int   nc = n0 + warp_n * 64 + nt * 8 + (lane & 3) * 2;
            float b0 = b[nc], b1 = b[nc + 1];
            float2 v0 = make_float2(d0 * (acc[mt][nt][0] + b0), d0 * (acc[mt][nt][1] + b1));
            float2 v1 = make_float2(d1 * (acc[mt][nt][2] + b0), d1 * (acc[mt][nt][3] + b1));
            *(float2*)&g_g[(size_t)r0 * CC + nc] = v0;
            *(float2*)&g_g[(size_t)r1 * CC + nc] = v1;
        }
    }
}

// ---------------- kernel 5: SpMM  out[i] = dis[i] * sum_{j in adj(i)} g[j] ----------------
__global__ __launch_bounds__(128) void k_spmm(float* __restrict__ out) {
    const int i    = blockIdx.x;
    const int tid  = threadIdx.x;
    const int lane = tid & 31;
    const int w    = tid >> 5;
    __shared__ unsigned rb[256];
    __shared__ int      sidx[1024];
    __shared__ int      wtot[4];

    rb[tid]       = g_bitmap[(size_t)i * 256 + tid];
    rb[tid + 128] = g_bitmap[(size_t)i * 256 + tid + 128];
    __syncthreads();

    unsigned w0 = rb[2 * tid], w1 = rb[2 * tid + 1];
    int cnt = __popc(w0) + __popc(w1);
    int inc = cnt;
#pragma unroll
    for (int o = 1; o < 32; o <<= 1) {
        int v = __shfl_up_sync(0xFFFFFFFFu, inc, o);
        if (lane >= o) inc += v;
    }
    if (lane == 31) wtot[w] = inc;
    __syncthreads();
    int base = inc - cnt;
    for (int q = 0; q < w; q++) base += wtot[q];
    int total = wtot[0] + wtot[1] + wtot[2] + wtot[3];

    const float4* __restrict__ g4 = (const float4*)g_g;
    float4 acc = make_float4(0.f, 0.f, 0.f, 0.f);
    float  di  = g_dis[i];

    if (total <= 1024) {
        int pos = base, jb = tid * 64;
        unsigned bb = w0;
        while (bb) { sidx[pos++] = jb + __ffs(bb) - 1; bb &= bb - 1; }
        bb = w1; jb += 32;
        while (bb) { sidx[pos++] = jb + __ffs(bb) - 1; bb &= bb - 1; }
        __syncthreads();

        int p = 0;
        for (; p + 8 <= total; p += 8) {
            float4 a0 = g4[(size_t)sidx[p + 0] * (CC / 4) + tid];
            float4 a1 = g4[(size_t)sidx[p + 1] * (CC / 4) + tid];
            float4 a2 = g4[(size_t)sidx[p + 2] * (CC / 4) + tid];
            float4 a3 = g4[(size_t)sidx[p + 3] * (CC / 4) + tid];
            float4 a4 = g4[(size_t)sidx[p + 4] * (CC / 4) + tid];
            float4 a5 = g4[(size_t)sidx[p + 5] * (CC / 4) + tid];
            float4 a6 = g4[(size_t)sidx[p + 6] * (CC / 4) + tid];
            float4 a7 = g4[(size_t)sidx[p + 7] * (CC / 4) + tid];
            acc.x += ((a0.x + a1.x) + (a2.x + a3.x)) + ((a4.x + a5.x) + (a6.x + a7.x));
            acc.y += ((a0.y + a1.y) + (a2.y + a3.y)) + ((a4.y + a5.y) + (a6.y + a7.y));
            acc.z += ((a0.z + a1.z) + (a2.z + a3.z)) + ((a4.z + a5.z) + (a6.z + a7.z));
            acc.w += ((a0.w + a1.w) + (a2.w + a3.w)) + ((a4.w + a5.w) + (a6.w + a7.w));
        }
        for (; p < total; p++) {
            float4 a0 = g4[(size_t)sidx[p] * (CC / 4) + tid];
            acc.x += a0.x; acc.y += a0.y; acc.z += a0.z; acc.w += a0.w;
        }
    } else {
        for (int ww = 0; ww < 256; ww++) {
            unsigned bits = rb[ww];
            while (bits) {
                int j = (ww << 5) + __ffs(bits) - 1;
                bits &= bits - 1;
                float4 gv = g4[(size_t)j * (CC / 4) + tid];
                acc.x += gv.x; acc.y += gv.y; acc.z += gv.z; acc.w += gv.w;
            }
        }
    }

    ((float4*)out)[(size_t)i * (CC / 4) + tid] =
        make_float4(di * acc.x, di * acc.y, di * acc.z, di * acc.w);
}

// ---------------- launch ----------------
extern "C" void kernel_launch(void* const* d_in, const int* in_sizes, int n_in,
                              void* d_out, int out_size) {
    const float* x  = nullptr;
    const void*  ei = nullptr;
    const float* W  = nullptr;
    const float* b  = nullptr;
    for (int i = 0; i < n_in; i++) {
        switch (in_sizes[i]) {
            case 4194304: x  = (const float*)d_in[i]; break;
            case 524288:  ei = d_in[i];               break;
            case 262144:  W  = (const float*)d_in[i]; break;
            case 512:     b  = (const float*)d_in[i]; break;
            default: break;
        }
    }
    float* o = (float*)d_out;

    cudaFuncSetAttribute(k_gemm_mma, cudaFuncAttributeMaxDynamicSharedMemorySize, 98304);

    k_clear<<<2048, 256>>>();
    k_dedup<<<(NE + NN + 255) / 256, 256>>>(ei);
    k_prep<<<4384, 256>>>(x, W);              // convX [0,4096) | convW [4096,4352) | dis [4352,4384)
    dim3 ggrid(CC / 128, NN / 128);           // (4, 64)
    k_gemm_mma<<<ggrid, 256, 98304>>>(b);
    k_spmm<<<NN, 128>>>(o);
}